// round 14
// baseline (speedup 1.0000x reference)
#include <cuda_runtime.h>
#include <cuda_fp16.h>
#include <math.h>

#define T_OBS   64
#define T_UNOBS 32
#define B       4096
#define D       4
#define H       256
#define G3      768    // 3*H
#define NSTEP   95     // 64 obs + 31 ar
#define NCTA    128    // row-local CTAs, 32 rows each, 1/SM
#define ROWS    32

// smem layout (bytes)
#define BSTRIDE   24        // halves per B-pipe row (16 + 8 pad) -> conflict-free frags
#define BST_BYTES (768 * BSTRIDE * 2)      // 36864 per stage
#define SGS       776       // floats per gate-stage row (768 + 8 pad)
#define SG_BYTES  (ROWS * SGS * 4)         // 99328
#define H16S      264       // halves per h16 row (256 + 8 pad)
#define SGH_OFF   0                         // aliases B-pipe region
#define BPIPE_OFF 0
#define SGX_OFF   (3 * BST_BYTES)           // 110592
#define H16_OFF   (SGX_OFF + SG_BYTES)      // 209920
#define APIPE_OFF (H16_OFF + ROWS * H16S * 2)  // 226816
#define AST_BYTES (ROWS * BSTRIDE * 2)      // 1536
#define SMEM_TOTAL (APIPE_OFF + 3 * AST_BYTES) // 231424

// ---------------- scratch (static device buffers; no allocation) ----------------
__device__ __align__(128) __half g_H1h[(size_t)T_OBS * B * H]; // stem out (fp16)
__device__ __align__(128) __half g_Wcp[G3 * H];  // folded x-weights, permuted rows (3u+g)
__device__ __align__(128) __half g_Wip[G3 * H];  // wi permuted
__device__ __align__(128) __half g_Whp[G3 * H];  // wh permuted
__device__ __align__(128) float  g_bc[G3];       // bi + wi @ b2 (gate-major)

// ---------------- helpers ----------------
__device__ __forceinline__ void mma_f16(float* c, const unsigned* a, const unsigned* b) {
    asm volatile(
        "mma.sync.aligned.m16n8k16.row.col.f32.f16.f16.f32 "
        "{%0,%1,%2,%3}, {%4,%5,%6,%7}, {%8,%9}, {%0,%1,%2,%3};"
        : "+f"(c[0]), "+f"(c[1]), "+f"(c[2]), "+f"(c[3])
        : "r"(a[0]), "r"(a[1]), "r"(a[2]), "r"(a[3]), "r"(b[0]), "r"(b[1]));
}

__device__ __forceinline__ void cp16(void* smem, const void* gmem) {
    unsigned s = (unsigned)__cvta_generic_to_shared(smem);
    asm volatile("cp.async.cg.shared.global [%0], [%1], 16;" :: "r"(s), "l"(gmem));
}

// ---------------- weight permutation: row g*256+u -> 3u+g ----------------
__global__ void round_w_kernel(const float* __restrict__ wi, const float* __restrict__ wh) {
    int i = blockIdx.x * blockDim.x + threadIdx.x;
    int j = i >> 8, k = i & 255;
    int p = 3 * (j & 255) + (j >> 8);
    g_Wip[p * H + k] = __float2half_rn(wi[i]);
    g_Whp[p * H + k] = __float2half_rn(wh[i]);
}

__global__ void wc_kernel(const float* __restrict__ wi, const float* __restrict__ w2,
                          const float* __restrict__ b2, const float* __restrict__ bi) {
    int j = blockIdx.x;   // 0..767 gate-major row
    int k = threadIdx.x;  // 0..255
    float acc = 0.f;
    for (int m = 0; m < H; m++)
        acc = fmaf(wi[j * H + m], w2[m * H + k], acc);
    int p = 3 * (j & 255) + (j >> 8);
    g_Wcp[p * H + k] = __float2half_rn(acc);
    if (k == 0) {
        float a = bi[j];
        for (int m = 0; m < H; m++)
            a = fmaf(wi[j * H + m], b2[m], a);
        g_bc[j] = a;
    }
}

// ---------------- stem: h1 = fp16(leaky_relu([x, dt] @ W1^T + b1)), 16 rows/block ----------------
__global__ void stem_kernel(const float* __restrict__ x_obs, const float* __restrict__ t_obs,
                            const float* __restrict__ w1, const float* __restrict__ b1) {
    __shared__ float w1s[H * 5];
    __shared__ float b1s[H];
    __shared__ float xts[16][5];
    int tid = threadIdx.x;
    int r0 = blockIdx.x * 16;

    for (int i = tid; i < H * 5; i += 256) w1s[i] = w1[i];
    b1s[tid] = b1[tid];
    if (tid < 16) {
        int row = r0 + tid;
        float4 xv = *(const float4*)(x_obs + (size_t)row * 4);
        xts[tid][0] = xv.x; xts[tid][1] = xv.y; xts[tid][2] = xv.z; xts[tid][3] = xv.w;
        int t = row >> 12;
        xts[tid][4] = (t == 0) ? 0.f : (t_obs[row] - t_obs[row - B]);
    }
    __syncthreads();

    int cq = (tid & 63) * 4;
    int lr0 = tid >> 6;
    float wv[4][5], bb[4];
#pragma unroll
    for (int c = 0; c < 4; c++) {
        bb[c] = b1s[cq + c];
#pragma unroll
        for (int k = 0; k < 5; k++) wv[c][k] = w1s[(cq + c) * 5 + k];
    }
#pragma unroll
    for (int rr = 0; rr < 4; rr++) {
        int lr = lr0 + rr * 4;
        int row = r0 + lr;
        float o[4];
#pragma unroll
        for (int c = 0; c < 4; c++) {
            float acc = bb[c];
#pragma unroll
            for (int k = 0; k < 5; k++)
                acc = fmaf(wv[c][k], xts[lr][k], acc);
            o[c] = (acc > 0.f) ? acc : 0.01f * acc;
        }
        __half2* dst = (__half2*)(g_H1h + (size_t)row * H + cq);
        dst[0] = __floats2half2_rn(o[0], o[1]);
        dst[1] = __floats2half2_rn(o[2], o[3]);
    }
}

// ---------------- one 32x768x256 GEMM pass -> SG (fp32 stage) ----------------
// APIPED: A streamed from global (obs gx). Otherwise A = resident h16 (smem).
// 8 warps, warp tile 32 rows x 96 cols (2 m16 x 12 n8), 16 k-chunks of 16.
template<bool APIPED>
__device__ __forceinline__ void gemm768(char* sm, const __half* __restrict__ Aglob,
                                        const __half* __restrict__ W, float* __restrict__ SG) {
    int tid = threadIdx.x, warp = tid >> 5, lane = tid & 31;
    int q = lane >> 2, r = lane & 3;
    int wn = warp;                      // 0..7
    const __half* h16 = (const __half*)(sm + H16_OFF);

    float acc[2][12][4];
#pragma unroll
    for (int mi = 0; mi < 2; mi++)
#pragma unroll
        for (int ni = 0; ni < 12; ni++)
#pragma unroll
            for (int j = 0; j < 4; j++) acc[mi][ni][j] = 0.f;

    // prologue: chunks 0,1
#pragma unroll
    for (int s = 0; s < 2; s++) {
        int k0 = s * 16;
        __half* Bst = (__half*)(sm + BPIPE_OFF + s * BST_BYTES);
#pragma unroll
        for (int l = 0; l < 6; l++) {
            int idx = l * 256 + tid;
            int row = idx >> 1, seg = idx & 1;
            cp16(&Bst[row * BSTRIDE + seg * 8], W + (size_t)row * H + k0 + seg * 8);
        }
        if (APIPED && tid < 64) {
            __half* Ast = (__half*)(sm + APIPE_OFF + s * AST_BYTES);
            int row = tid >> 1, seg = tid & 1;
            cp16(&Ast[row * BSTRIDE + seg * 8], Aglob + (size_t)row * H + k0 + seg * 8);
        }
        asm volatile("cp.async.commit_group;");
    }

#pragma unroll 1
    for (int kc = 0; kc < 16; kc++) {
        asm volatile("cp.async.wait_group 1;");
        __syncthreads();
        int buf = kc % 3;
        const __half* Bst = (const __half*)(sm + BPIPE_OFF + buf * BST_BYTES);

        unsigned af[2][4], bf[12][2];
        if (APIPED) {
            const __half* Ast = (const __half*)(sm + APIPE_OFF + buf * AST_BYTES);
#pragma unroll
            for (int mi = 0; mi < 2; mi++) {
                int rm = mi * 16 + q;
                af[mi][0] = *(const unsigned*)&Ast[rm * BSTRIDE + 2 * r];
                af[mi][1] = *(const unsigned*)&Ast[(rm + 8) * BSTRIDE + 2 * r];
                af[mi][2] = *(const unsigned*)&Ast[rm * BSTRIDE + 2 * r + 8];
                af[mi][3] = *(const unsigned*)&Ast[(rm + 8) * BSTRIDE + 2 * r + 8];
            }
        } else {
            int cb = kc * 16;
#pragma unroll
            for (int mi = 0; mi < 2; mi++) {
                int rm = mi * 16 + q;
                af[mi][0] = *(const unsigned*)&h16[rm * H16S + cb + 2 * r];
                af[mi][1] = *(const unsigned*)&h16[(rm + 8) * H16S + cb + 2 * r];
                af[mi][2] = *(const unsigned*)&h16[rm * H16S + cb + 2 * r + 8];
                af[mi][3] = *(const unsigned*)&h16[(rm + 8) * H16S + cb + 2 * r + 8];
            }
        }
#pragma unroll
        for (int ni = 0; ni < 12; ni++) {
            int cn = wn * 96 + ni * 8 + q;
            bf[ni][0] = *(const unsigned*)&Bst[cn * BSTRIDE + 2 * r];
            bf[ni][1] = *(const unsigned*)&Bst[cn * BSTRIDE + 2 * r + 8];
        }
#pragma unroll
        for (int mi = 0; mi < 2; mi++)
#pragma unroll
            for (int ni = 0; ni < 12; ni++)
                mma_f16(acc[mi][ni], af[mi], bf[ni]);

        // issue chunk kc+2
        if (kc + 2 < 16) {
            int s = (kc + 2) % 3;
            int k0 = (kc + 2) * 16;
            __half* Bn = (__half*)(sm + BPIPE_OFF + s * BST_BYTES);
#pragma unroll
            for (int l = 0; l < 6; l++) {
                int idx = l * 256 + tid;
                int row = idx >> 1, seg = idx & 1;
                cp16(&Bn[row * BSTRIDE + seg * 8], W + (size_t)row * H + k0 + seg * 8);
            }
            if (APIPED && tid < 64) {
                __half* An = (__half*)(sm + APIPE_OFF + s * AST_BYTES);
                int row = tid >> 1, seg = tid & 1;
                cp16(&An[row * BSTRIDE + seg * 8], Aglob + (size_t)row * H + k0 + seg * 8);
            }
        }
        asm volatile("cp.async.commit_group;");
    }

    __syncthreads();   // all frag reads done before staging may overwrite B-pipe
#pragma unroll
    for (int mi = 0; mi < 2; mi++) {
        int rm = mi * 16 + q;
#pragma unroll
        for (int ni = 0; ni < 12; ni++) {
            int col = wn * 96 + ni * 8 + 2 * r;
            *(float2*)&SG[rm * SGS + col]       = make_float2(acc[mi][ni][0], acc[mi][ni][1]);
            *(float2*)&SG[(rm + 8) * SGS + col] = make_float2(acc[mi][ni][2], acc[mi][ni][3]);
        }
    }
}

// ---------------- persistent row-local recurrence: zero inter-CTA sync ----------------
__global__ __launch_bounds__(256, 1) void rnn_rowlocal(
    const float* __restrict__ bi, const float* __restrict__ bh,
    float* __restrict__ zs_base) {
    extern __shared__ char sm[];
    float* SGX = (float*)(sm + SGX_OFF);
    float* SGH = (float*)(sm + SGH_OFF);      // aliases B-pipe
    __half* h16 = (__half*)(sm + H16_OFF);

    int tid = threadIdx.x;
    int b0 = blockIdx.x * ROWS;

    // init resident hidden state: smem fp16 + per-thread fp32 master
    for (int i = tid; i < ROWS * H16S; i += 256) h16[i] = __float2half(0.f);
    float hreg[32];
#pragma unroll
    for (int i = 0; i < 32; i++) hreg[i] = 0.f;
    __syncthreads();

    for (int step = 0; step < NSTEP; step++) {
        bool ar = (step >= T_OBS);

        // pass 1: gx -> SGX
        if (!ar)
            gemm768<true>(sm, g_H1h + ((size_t)step * B + b0) * H, g_Wcp, SGX);
        else
            gemm768<false>(sm, nullptr, g_Wip, SGX);
        __syncthreads();

        // pass 2: gh -> SGH (stages over B-pipe after its last read)
        gemm768<false>(sm, nullptr, g_Whp, SGH);
        __syncthreads();

        // fused GRU (row-local, h in registers)
        const float* bx = ar ? bi : g_bc;
        float* zso = nullptr;
        if (step == T_OBS - 1)      zso = zs_base;
        else if (ar)                zso = zs_base + (size_t)(step - (T_OBS - 1)) * B * H;

#pragma unroll
        for (int it = 0; it < 32; it++) {
            int idx = it * 256 + tid;
            int row = idx >> 8;
            int u = idx & 255;
            const float* gx = SGX + row * SGS + 3 * u;
            const float* gh = SGH + row * SGS + 3 * u;
            float gxr = gx[0] + bx[u];
            float gxz = gx[1] + bx[256 + u];
            float gxn = gx[2] + bx[512 + u];
            float ghr = gh[0] + bh[u];
            float ghz = gh[1] + bh[256 + u];
            float ghn = gh[2] + bh[512 + u];
            float rr = 1.f / (1.f + expf(-(gxr + ghr)));
            float ug = 1.f / (1.f + expf(-(gxz + ghz)));
            float nn = tanhf(gxn + rr * ghn);
            float hv = (1.f - ug) * nn + ug * hreg[it];
            hreg[it] = hv;
            h16[row * H16S + u] = __float2half_rn(hv);
            if (zso) zso[(size_t)(b0 + row) * H + u] = hv;
        }
        __syncthreads();   // GRU done before next step touches h16 / B-pipe
    }
}

// ---------------- head: x_hats = zs @ head_w^T + head_b ----------------
__global__ void head_kernel(const float* __restrict__ zs, const float* __restrict__ head_w,
                            const float* __restrict__ head_b, float* __restrict__ xh) {
    int row = blockIdx.x * 8 + (threadIdx.x >> 5);
    int lane = threadIdx.x & 31;
    const float* z = zs + (size_t)row * H;
    float acc[4] = {0.f, 0.f, 0.f, 0.f};
    for (int c = lane; c < H; c += 32) {
        float zv = z[c];
#pragma unroll
        for (int d = 0; d < 4; d++)
            acc[d] = fmaf(zv, head_w[d * H + c], acc[d]);
    }
#pragma unroll
    for (int d = 0; d < 4; d++)
        for (int off = 16; off; off >>= 1)
            acc[d] += __shfl_xor_sync(0xFFFFFFFFu, acc[d], off);
    if (lane < 4)
        xh[(size_t)row * 4 + lane] = acc[lane] + head_b[lane];
}

// ---------------- launch ----------------
extern "C" void kernel_launch(void* const* d_in, const int* in_sizes, int n_in,
                              void* d_out, int out_size) {
    const float* x_obs   = (const float*)d_in[0];
    const float* t_obs   = (const float*)d_in[1];
    const float* stem_w1 = (const float*)d_in[3];
    const float* stem_b1 = (const float*)d_in[4];
    const float* stem_w2 = (const float*)d_in[5];
    const float* stem_b2 = (const float*)d_in[6];
    const float* gru_wi  = (const float*)d_in[7];
    const float* gru_wh  = (const float*)d_in[8];
    const float* gru_bi  = (const float*)d_in[9];
    const float* gru_bh  = (const float*)d_in[10];
    const float* head_w  = (const float*)d_in[11];
    const float* head_b  = (const float*)d_in[12];

    float* out    = (float*)d_out;
    float* x_hats = out;                                 // [32,4096,4]
    float* zs     = out + (size_t)T_UNOBS * B * D;       // [32,4096,256]

    cudaFuncSetAttribute(rnn_rowlocal,
                         cudaFuncAttributeMaxDynamicSharedMemorySize, SMEM_TOTAL);

    round_w_kernel<<<(G3 * H) / 256, 256>>>(gru_wi, gru_wh);
    wc_kernel<<<G3, H>>>(gru_wi, stem_w2, stem_b2, gru_bi);
    stem_kernel<<<T_OBS * B / 16, 256>>>(x_obs, t_obs, stem_w1, stem_b1);

    rnn_rowlocal<<<NCTA, 256, SMEM_TOTAL>>>(gru_bi, gru_bh, zs);

    head_kernel<<<(T_UNOBS * B) / 8, 256>>>(zs, head_w, head_b, x_hats);
}

// round 15
// speedup vs baseline: 1.4811x; 1.4811x over previous
#include <cuda_runtime.h>
#include <cuda_fp16.h>
#include <math.h>

#define T_OBS   64
#define T_UNOBS 32
#define B       4096
#define D       4
#define H       256
#define G3      768    // 3*H
#define NSTEP   95     // 64 obs + 31 ar
#define NCTA    296    // 2 CTAs/SM on 148 SMs -> co-resident
#define SLABS   32     // m-slabs of 128 rows
#define GRUCH   256    // GRU chunks (16 rows), chunk r in slab r>>3
#define STAGES  3
#define BK      64     // k-chunk in halves
#define SROW    72     // smem row stride in halves (64 + 8 pad)

// ---------------- scratch (static device buffers; no allocation) ----------------
__device__ __align__(128) __half g_H1h[(size_t)T_OBS * B * H]; // stem out (fp16)
__device__ __align__(128) __half g_Wch[G3 * H];                // wi @ W2 folded (fp16)
__device__ __align__(128) float  g_bc[G3];                     // bi + wi @ b2 (fp32)
__device__ __align__(128) __half g_Wih[G3 * H];                // wi (fp16)
__device__ __align__(128) __half g_Whh[G3 * H];                // wh (fp16)
__device__ __align__(128) __half g_hth[2][B * H];              // hidden fp16 (ping-pong)
__device__ __align__(128) float  g_G[2][(size_t)B * 2 * G3];   // gates [gx | gh], parity-buffered
__device__ unsigned g_tileCnt[SLABS];   // 12 signals/slab/step (monotone)
__device__ unsigned g_gruCnt[SLABS];    // 8 signals/slab/step (monotone)

// ---------------- helpers ----------------
__device__ __forceinline__ void mma_f16(float* c, const unsigned* a, const unsigned* b) {
    asm volatile(
        "mma.sync.aligned.m16n8k16.row.col.f32.f16.f16.f32 "
        "{%0,%1,%2,%3}, {%4,%5,%6,%7}, {%8,%9}, {%0,%1,%2,%3};"
        : "+f"(c[0]), "+f"(c[1]), "+f"(c[2]), "+f"(c[3])
        : "r"(a[0]), "r"(a[1]), "r"(a[2]), "r"(a[3]), "r"(b[0]), "r"(b[1]));
}

__device__ __forceinline__ void ldsm_x4(unsigned* d, unsigned saddr) {
    asm volatile("ldmatrix.sync.aligned.m8n8.x4.shared.b16 {%0,%1,%2,%3}, [%4];"
        : "=r"(d[0]), "=r"(d[1]), "=r"(d[2]), "=r"(d[3]) : "r"(saddr));
}

__device__ __forceinline__ void cp16(void* smem, const void* gmem) {
    unsigned s = (unsigned)__cvta_generic_to_shared(smem);
    asm volatile("cp.async.cg.shared.global [%0], [%1], 16;" :: "r"(s), "l"(gmem));
}

__device__ __forceinline__ void spin_ge(unsigned* p, unsigned tgt) {
    if (threadIdx.x == 0) {
        unsigned v;
        do {
            asm volatile("ld.acquire.gpu.u32 %0, [%1];" : "=r"(v) : "l"(p) : "memory");
            if (v < tgt) __nanosleep(32);
        } while (v < tgt);
    }
    __syncthreads();
}

__device__ __forceinline__ void signal(unsigned* p) {
    __syncthreads();
    if (threadIdx.x == 0) {
        __threadfence();
        atomicAdd(p, 1u);
    }
}

// ---------------- init ----------------
__global__ void zero_kernel() {
    int idx = blockIdx.x * blockDim.x + threadIdx.x;
    g_hth[0][idx] = __float2half(0.f);
    if (idx < SLABS) { g_tileCnt[idx] = 0u; g_gruCnt[idx] = 0u; }
}

__global__ void round_w_kernel(const float* __restrict__ wi, const float* __restrict__ wh) {
    int i = blockIdx.x * blockDim.x + threadIdx.x;
    g_Wih[i] = __float2half_rn(wi[i]);
    g_Whh[i] = __float2half_rn(wh[i]);
}

__global__ void wc_kernel(const float* __restrict__ wi, const float* __restrict__ w2,
                          const float* __restrict__ b2, const float* __restrict__ bi) {
    int j = blockIdx.x;   // 0..767
    int k = threadIdx.x;  // 0..255
    float acc = 0.f;
    for (int m = 0; m < H; m++)
        acc = fmaf(wi[j * H + m], w2[m * H + k], acc);
    g_Wch[j * H + k] = __float2half_rn(acc);
    if (k == 0) {
        float a = bi[j];
        for (int m = 0; m < H; m++)
            a = fmaf(wi[j * H + m], b2[m], a);
        g_bc[j] = a;
    }
}

// ---------------- stem: h1 = fp16(leaky_relu([x, dt] @ W1^T + b1)), 16 rows/block ----------------
__global__ void stem_kernel(const float* __restrict__ x_obs, const float* __restrict__ t_obs,
                            const float* __restrict__ w1, const float* __restrict__ b1) {
    __shared__ float w1s[H * 5];
    __shared__ float b1s[H];
    __shared__ float xts[16][5];
    int tid = threadIdx.x;
    int r0 = blockIdx.x * 16;

    for (int i = tid; i < H * 5; i += 256) w1s[i] = w1[i];
    b1s[tid] = b1[tid];
    if (tid < 16) {
        int row = r0 + tid;
        float4 xv = *(const float4*)(x_obs + (size_t)row * 4);
        xts[tid][0] = xv.x; xts[tid][1] = xv.y; xts[tid][2] = xv.z; xts[tid][3] = xv.w;
        int t = row >> 12;
        xts[tid][4] = (t == 0) ? 0.f : (t_obs[row] - t_obs[row - B]);
    }
    __syncthreads();

    int cq = (tid & 63) * 4;
    int lr0 = tid >> 6;
    float wv[4][5], bb[4];
#pragma unroll
    for (int c = 0; c < 4; c++) {
        bb[c] = b1s[cq + c];
#pragma unroll
        for (int k = 0; k < 5; k++) wv[c][k] = w1s[(cq + c) * 5 + k];
    }
#pragma unroll
    for (int rr = 0; rr < 4; rr++) {
        int lr = lr0 + rr * 4;
        int row = r0 + lr;
        float o[4];
#pragma unroll
        for (int c = 0; c < 4; c++) {
            float acc = bb[c];
#pragma unroll
            for (int k = 0; k < 5; k++)
                acc = fmaf(wv[c][k], xts[lr][k], acc);
            o[c] = (acc > 0.f) ? acc : 0.01f * acc;
        }
        __half2* dst = (__half2*)(g_H1h + (size_t)row * H + cq);
        dst[0] = __floats2half2_rn(o[0], o[1]);
        dst[1] = __floats2half2_rn(o[2], o[3]);
    }
}

// ---------------- persistent recurrence: BK=64 + ldmatrix + reg-resident h ----------------
// Tile ids: 0..191 = x-path (tn 0..5), 192..383 = h-path (tn 6..11).
// Ranks 0..103 own x tiles {rank, rank+104<192}; ranks 104..295 own h tile {rank+88}.
__global__ __launch_bounds__(256, 2) void rnn_persistent(
    const float* __restrict__ bi, const float* __restrict__ bh,
    float* __restrict__ zs_base) {
    extern __shared__ __half smh[];
    __half (*As)[128 * SROW] = (__half (*)[128 * SROW])smh;
    __half (*Bs)[128 * SROW] = (__half (*)[128 * SROW])(smh + STAGES * 128 * SROW);

    int tid = threadIdx.x, warp = tid >> 5, lane = tid & 31;
    int q = lane >> 2, r = lane & 3;
    int wm = warp & 3, wn = warp >> 2;
    int rank = blockIdx.x;

    // static tile list per rank
    int myTiles[2];
    int nT = 0;
    if (rank < 104) {
        myTiles[nT++] = rank;
        if (rank + 104 < 192) myTiles[nT++] = rank + 104;
    } else {
        myTiles[nT++] = rank + 88;    // 192..383
    }

    // ldmatrix lane-address components (element offsets within a stage)
    // A (m16k16 x4): row = rmBase + (lane&15), koff += (lane>>4)*8
    int aRowOff = (lane & 15) * SROW + ((lane >> 4) << 3);
    // B (two n8k16 mats x4): nrow = nBase + ((lane>>4)&1)*8 + (lane&7), koff += ((lane>>3)&1)*8
    int bRowOff = (((lane >> 4) & 1) * 8 + (lane & 7)) * SROW + (((lane >> 3) & 1) << 3);

    // fp32 hidden master: GRU rank owns rows 16*rank..16*rank+15 (4 float4 per thread)
    float4 hpr[4];
#pragma unroll
    for (int j = 0; j < 4; j++) hpr[j] = make_float4(0.f, 0.f, 0.f, 0.f);

    for (int step = 0; step < NSTEP; step++) {
        int par = step & 1;
        bool ar = (step >= T_OBS);
        const __half* hA = g_hth[par];
        float* Gw = g_G[par];

        // ---- GEMM tiles (dataflow gated per slab) ----
        for (int ti = 0; ti < nT; ti++) {
            int tile = myTiles[ti];
            int tn = tile >> 5;        // 0..11
            int tm = tile & 31;        // slab
            bool needsH = ar || (tn >= 6);
            unsigned tgt = needsH ? 8u * step : (step ? 8u * (step - 1) : 0u);
            if (tgt) spin_ge(&g_gruCnt[tm], tgt);

            const __half* A;
            const __half* W;
            if (tn < 6) {
                A = ar ? hA : (g_H1h + (size_t)step * B * H);
                W = ar ? g_Wih : g_Wch;
            } else {
                A = hA;
                W = g_Whh;
            }
            int wrow = (tn < 6 ? tn : tn - 6) * 128;
            int gcol = tn * 128;
            int mbase = tm * 128;
            const __half* Abase = A + (size_t)mbase * H;
            const __half* Wbase = W + (size_t)wrow * H;

            float acc[2][8][4] = {};

            __syncthreads();   // smem reuse guard across tiles

            // prologue: stages 0,1 (each 128 rows x 64 halves per operand)
#pragma unroll
            for (int s = 0; s < 2; s++) {
                int k0 = s * BK;
#pragma unroll
                for (int l = 0; l < 4; l++) {
                    int idx = l * 256 + tid;
                    int row = idx >> 3, seg = idx & 7;
                    cp16(&As[s][row * SROW + seg * 8], Abase + (size_t)row * H + k0 + seg * 8);
                }
#pragma unroll
                for (int l = 0; l < 4; l++) {
                    int idx = l * 256 + tid;
                    int row = idx >> 3, seg = idx & 7;
                    cp16(&Bs[s][row * SROW + seg * 8], Wbase + (size_t)row * H + k0 + seg * 8);
                }
                asm volatile("cp.async.commit_group;");
            }

#pragma unroll 1
            for (int kc = 0; kc < 4; kc++) {       // 4 chunks of 64
                asm volatile("cp.async.wait_group 1;");
                __syncthreads();
                int buf = kc % 3;
                unsigned AbS = (unsigned)__cvta_generic_to_shared(As[buf]);
                unsigned BbS = (unsigned)__cvta_generic_to_shared(Bs[buf]);

                if (kc + 2 < 4) {
                    int s = (kc + 2) % 3;
                    int k0 = (kc + 2) * BK;
#pragma unroll
                    for (int l = 0; l < 4; l++) {
                        int idx = l * 256 + tid;
                        int row = idx >> 3, seg = idx & 7;
                        cp16(&As[s][row * SROW + seg * 8], Abase + (size_t)row * H + k0 + seg * 8);
                    }
#pragma unroll
                    for (int l = 0; l < 4; l++) {
                        int idx = l * 256 + tid;
                        int row = idx >> 3, seg = idx & 7;
                        cp16(&Bs[s][row * SROW + seg * 8], Wbase + (size_t)row * H + k0 + seg * 8);
                    }
                }
                asm volatile("cp.async.commit_group;");

#pragma unroll
                for (int ks = 0; ks < 4; ks++) {   // 4 k16 steps per chunk
                    int kk = ks * 16;
                    unsigned af[2][4], bf[8][2];
#pragma unroll
                    for (int mi = 0; mi < 2; mi++) {
                        int rmBase = wm * 32 + mi * 16;
                        ldsm_x4(af[mi], AbS + (unsigned)(rmBase * SROW + kk + aRowOff) * 2u);
                    }
#pragma unroll
                    for (int np = 0; np < 4; np++) {   // ni pairs
                        unsigned bq[4];
                        int nBase = wn * 64 + np * 16;
                        ldsm_x4(bq, BbS + (unsigned)(nBase * SROW + kk + bRowOff) * 2u);
                        bf[2 * np][0] = bq[0]; bf[2 * np][1] = bq[1];
                        bf[2 * np + 1][0] = bq[2]; bf[2 * np + 1][1] = bq[3];
                    }
#pragma unroll
                    for (int mi = 0; mi < 2; mi++)
#pragma unroll
                        for (int ni = 0; ni < 8; ni++)
                            mma_f16(acc[mi][ni], af[mi], bf[ni]);
                }
            }

#pragma unroll
            for (int mi = 0; mi < 2; mi++) {
                int row = mbase + wm * 32 + mi * 16 + q;
#pragma unroll
                for (int ni = 0; ni < 8; ni++) {
                    int cl = wn * 64 + ni * 8 + 2 * r;
                    *(float2*)&Gw[(size_t)row * (2 * G3) + gcol + cl] =
                        make_float2(acc[mi][ni][0], acc[mi][ni][1]);
                    *(float2*)&Gw[(size_t)(row + 8) * (2 * G3) + gcol + cl] =
                        make_float2(acc[mi][ni][2], acc[mi][ni][3]);
                }
            }
            signal(&g_tileCnt[tm]);
        }

        // ---- GRU chunk (16 rows), h master in registers ----
        if (rank < GRUCH) {
            int slab = rank >> 3;
            spin_ge(&g_tileCnt[slab], 12u * (step + 1));

            const float* bxi = ar ? bi : g_bc;
            __half* htn = g_hth[par ^ 1];
            float* zs_out = nullptr;
            if (step == T_OBS - 1)      zs_out = zs_base;
            else if (ar)                zs_out = zs_base + (size_t)(step - (T_OBS - 1)) * B * H;

            int row0 = rank * 16;
#pragma unroll
            for (int j = 0; j < 4; j++) {
                int i = tid + j * 256;
                int b = row0 + (i >> 6);
                int m4 = (i & 63) * 4;
                const float* g = Gw + (size_t)b * (2 * G3);
                float4 rx = *(const float4*)(g + m4);
                float4 zx = *(const float4*)(g + H + m4);
                float4 nx = *(const float4*)(g + 2 * H + m4);
                float4 rh = *(const float4*)(g + G3 + m4);
                float4 zh = *(const float4*)(g + G3 + H + m4);
                float4 nh = *(const float4*)(g + G3 + 2 * H + m4);
                float4 br = *(const float4*)(bxi + m4);
                float4 bz = *(const float4*)(bxi + H + m4);
                float4 bn = *(const float4*)(bxi + 2 * H + m4);
                float4 cr = *(const float4*)(bh + m4);
                float4 cz = *(const float4*)(bh + H + m4);
                float4 cn = *(const float4*)(bh + 2 * H + m4);
                float4 hp = hpr[j];
                float4 hn4;
#pragma unroll
                for (int c = 0; c < 4; c++) {
                    float gxr = (&rx.x)[c] + (&br.x)[c];
                    float gxz = (&zx.x)[c] + (&bz.x)[c];
                    float gxn = (&nx.x)[c] + (&bn.x)[c];
                    float ghr = (&rh.x)[c] + (&cr.x)[c];
                    float ghz = (&zh.x)[c] + (&cz.x)[c];
                    float ghn = (&nh.x)[c] + (&cn.x)[c];
                    float rr = 1.f / (1.f + expf(-(gxr + ghr)));
                    float ug = 1.f / (1.f + expf(-(gxz + ghz)));
                    float nn = tanhf(gxn + rr * ghn);
                    (&hn4.x)[c] = (1.f - ug) * nn + ug * (&hp.x)[c];
                }
                hpr[j] = hn4;
                *(__half2*)(htn + (size_t)b * H + m4)     = __floats2half2_rn(hn4.x, hn4.y);
                *(__half2*)(htn + (size_t)b * H + m4 + 2) = __floats2half2_rn(hn4.z, hn4.w);
                if (zs_out) *(float4*)(zs_out + (size_t)b * H + m4) = hn4;
            }
            signal(&g_gruCnt[slab]);
        }
    }
}

// ---------------- head: x_hats = zs @ head_w^T + head_b ----------------
__global__ void head_kernel(const float* __restrict__ zs, const float* __restrict__ head_w,
                            const float* __restrict__ head_b, float* __restrict__ xh) {
    int row = blockIdx.x * 8 + (threadIdx.x >> 5);
    int lane = threadIdx.x & 31;
    const float* z = zs + (size_t)row * H;
    float acc[4] = {0.f, 0.f, 0.f, 0.f};
    for (int c = lane; c < H; c += 32) {
        float zv = z[c];
#pragma unroll
        for (int d = 0; d < 4; d++)
            acc[d] = fmaf(zv, head_w[d * H + c], acc[d]);
    }
#pragma unroll
    for (int d = 0; d < 4; d++)
        for (int off = 16; off; off >>= 1)
            acc[d] += __shfl_xor_sync(0xFFFFFFFFu, acc[d], off);
    if (lane < 4)
        xh[(size_t)row * 4 + lane] = acc[lane] + head_b[lane];
}

// ---------------- launch ----------------
extern "C" void kernel_launch(void* const* d_in, const int* in_sizes, int n_in,
                              void* d_out, int out_size) {
    const float* x_obs   = (const float*)d_in[0];
    const float* t_obs   = (const float*)d_in[1];
    const float* stem_w1 = (const float*)d_in[3];
    const float* stem_b1 = (const float*)d_in[4];
    const float* stem_w2 = (const float*)d_in[5];
    const float* stem_b2 = (const float*)d_in[6];
    const float* gru_wi  = (const float*)d_in[7];
    const float* gru_wh  = (const float*)d_in[8];
    const float* gru_bi  = (const float*)d_in[9];
    const float* gru_bh  = (const float*)d_in[10];
    const float* head_w  = (const float*)d_in[11];
    const float* head_b  = (const float*)d_in[12];

    float* out    = (float*)d_out;
    float* x_hats = out;                                 // [32,4096,4]
    float* zs     = out + (size_t)T_UNOBS * B * D;       // [32,4096,256]

    const int SMEM = STAGES * 128 * SROW * 2 * 2;        // 110592 bytes
    cudaFuncSetAttribute(rnn_persistent,
                         cudaFuncAttributeMaxDynamicSharedMemorySize, SMEM);

    zero_kernel<<<(B * H) / 256, 256>>>();
    round_w_kernel<<<(G3 * H) / 256, 256>>>(gru_wi, gru_wh);
    wc_kernel<<<G3, H>>>(gru_wi, stem_w2, stem_b2, gru_bi);
    stem_kernel<<<T_OBS * B / 16, 256>>>(x_obs, t_obs, stem_w1, stem_b1);

    rnn_persistent<<<NCTA, 256, SMEM>>>(gru_bi, gru_bh, zs);

    head_kernel<<<(T_UNOBS * B) / 8, 256>>>(zs, head_w, head_b, x_hats);
}